// round 13
// baseline (speedup 1.0000x reference)
#include <cuda_runtime.h>
#include <cuda_bf16.h>
#include <math.h>
#include <stdint.h>

// ContrastiveLoss: N=16384, D=128.
// sq[i][j] = max(sq1[i]+sq2[j]-2*dot, 0); exp(-sq)==0 in fp32 for sq>~104.
// int8 mma.sync (m16n8k32.s8) GEMM as a coarse filter: q = round(20*x),
// dot ~= (s32 dot)/400, worst-case sq error < 14 -> EST_CUT=119 margin.
// Exact fp32 recompute for the (essentially never occurring) near pairs.
// Rows with any |20*x| > 127 get -1e9 bias on the filtered norm -> exact path.
//
// R13 = R12 (best, 269.0 us) + ONE isolated change: epilogue s1 values are
// staged to SMEM with the existing staging phase and read via LDS, replacing
// 8 scattered per-thread global loads. This deconfounds R9 (which bundled
// this change with cp.async staging and regressed). MMA loop untouched.

#define D    128
#define BM   128
#define BN   128
#define NMAX 16384
#define GT_MAX (NMAX / BN)
#define SQ_CUT  105.0f
#define EST_CUT 119.0f
#define QS      20.0f        // quant scale
#define INV2S2  0.005f       // 2 / (QS*QS)

// ---- static device scratch ----
__device__ float  g_sq1[NMAX];     // clean |x1_i|^2
__device__ float  g_sq2[NMAX];     // clean |x2_j|^2
__device__ float  g_f1[NMAX];      // sq1 - (dirty ? 1e9 : 0)   (filter copy)
__device__ float  g_f2[NMAX];
__device__ float  g_possq[NMAX];
__device__ char   g_a8[(size_t)NMAX * D];
__device__ char   g_b8[(size_t)NMAX * D];
__device__ float  g_part[(size_t)GT_MAX * NMAX];
__device__ double g_blk[NMAX / 256][3];

// ---- SMEM layout: padded int8 rows, 144B stride (conflict-free ldmatrix) --
#define ROWB       144
#define SMEM_A     0
#define SMEM_B     (128 * ROWB)              // 18432
#define SMEM_PART  (2 * 128 * ROWB)          // 36864: float[4][128]
#define SMEM_H     (SMEM_PART + 2048)        // 38912: float[128] filtered sq2
#define SMEM_S1    (SMEM_H + 512)            // 39424: float[128] filtered sq1
#define SMEM_TOTAL (SMEM_S1 + 512 + 64)

__device__ __forceinline__ uint32_t smem_u32(const void* p) {
    uint32_t a;
    asm("{ .reg .u64 t; cvta.to.shared.u64 t, %1; cvt.u32.u64 %0, t; }"
        : "=r"(a) : "l"(p));
    return a;
}
__device__ __forceinline__ void ldsm4(uint32_t* r, uint32_t addr) {
    asm volatile("ldmatrix.sync.aligned.m8n8.x4.shared.b16 {%0,%1,%2,%3}, [%4];"
                 : "=r"(r[0]), "=r"(r[1]), "=r"(r[2]), "=r"(r[3]) : "r"(addr));
}
__device__ __forceinline__ void ldsm2(uint32_t* r, uint32_t addr) {
    asm volatile("ldmatrix.sync.aligned.m8n8.x2.shared.b16 {%0,%1}, [%2];"
                 : "=r"(r[0]), "=r"(r[1]) : "r"(addr));
}
__device__ __forceinline__ void imma16832(int* d, const uint32_t* a, const uint32_t* b) {
    asm volatile(
        "mma.sync.aligned.m16n8k32.row.col.s32.s8.s8.s32 "
        "{%0,%1,%2,%3}, {%4,%5,%6,%7}, {%8,%9}, {%0,%1,%2,%3};"
        : "+r"(d[0]), "+r"(d[1]), "+r"(d[2]), "+r"(d[3])
        : "r"(a[0]), "r"(a[1]), "r"(a[2]), "r"(a[3]), "r"(b[0]), "r"(b[1]));
}

__device__ __forceinline__ int quant1(float x, float& mx) {
    float f = x * QS;
    mx = fmaxf(mx, fabsf(f));
    f = fmaxf(fminf(f, 127.0f), -127.0f);
    return __float2int_rn(f);
}

// ============================================================================
// Kernel 0: row norms, pos_sq, int8 quant + dirty flags. 2 rows per warp.
// ============================================================================
__global__ void prep_kernel(const float* __restrict__ x1,
                            const float* __restrict__ x2, int n) {
    int warp = (blockIdx.x * blockDim.x + threadIdx.x) >> 5;
    int lane = threadIdx.x & 31;
    int r0 = warp * 2;
    if (r0 >= n) return;
    int r1 = r0 + 1;

    float4 va0 = reinterpret_cast<const float4*>(x1 + (size_t)r0 * D)[lane];
    float4 va1 = reinterpret_cast<const float4*>(x1 + (size_t)r1 * D)[lane];
    float4 vb0 = reinterpret_cast<const float4*>(x2 + (size_t)r0 * D)[lane];
    float4 vb1 = reinterpret_cast<const float4*>(x2 + (size_t)r1 * D)[lane];

    float mxa0 = 0.0f, mxb0 = 0.0f, mxa1 = 0.0f, mxb1 = 0.0f;
    char4 qa0, qb0, qa1, qb1;
    qa0.x = (char)quant1(va0.x, mxa0); qa0.y = (char)quant1(va0.y, mxa0);
    qa0.z = (char)quant1(va0.z, mxa0); qa0.w = (char)quant1(va0.w, mxa0);
    qa1.x = (char)quant1(va1.x, mxa1); qa1.y = (char)quant1(va1.y, mxa1);
    qa1.z = (char)quant1(va1.z, mxa1); qa1.w = (char)quant1(va1.w, mxa1);
    qb0.x = (char)quant1(vb0.x, mxb0); qb0.y = (char)quant1(vb0.y, mxb0);
    qb0.z = (char)quant1(vb0.z, mxb0); qb0.w = (char)quant1(vb0.w, mxb0);
    qb1.x = (char)quant1(vb1.x, mxb1); qb1.y = (char)quant1(vb1.y, mxb1);
    qb1.z = (char)quant1(vb1.z, mxb1); qb1.w = (char)quant1(vb1.w, mxb1);
    reinterpret_cast<char4*>(g_a8 + (size_t)r0 * D)[lane] = qa0;
    reinterpret_cast<char4*>(g_a8 + (size_t)r1 * D)[lane] = qa1;
    reinterpret_cast<char4*>(g_b8 + (size_t)r0 * D)[lane] = qb0;
    reinterpret_cast<char4*>(g_b8 + (size_t)r1 * D)[lane] = qb1;

    unsigned dA0 = __ballot_sync(0xffffffffu, mxa0 > 127.0f);
    unsigned dA1 = __ballot_sync(0xffffffffu, mxa1 > 127.0f);
    unsigned dB0 = __ballot_sync(0xffffffffu, mxb0 > 127.0f);
    unsigned dB1 = __ballot_sync(0xffffffffu, mxb1 > 127.0f);

    float s10 = va0.x*va0.x + va0.y*va0.y + va0.z*va0.z + va0.w*va0.w;
    float s11 = va1.x*va1.x + va1.y*va1.y + va1.z*va1.z + va1.w*va1.w;
    float s20 = vb0.x*vb0.x + vb0.y*vb0.y + vb0.z*vb0.z + vb0.w*vb0.w;
    float s21 = vb1.x*vb1.x + vb1.y*vb1.y + vb1.z*vb1.z + vb1.w*vb1.w;
    float dx0 = va0.x - vb0.x, dy0 = va0.y - vb0.y,
          dz0 = va0.z - vb0.z, dw0 = va0.w - vb0.w;
    float dx1 = va1.x - vb1.x, dy1 = va1.y - vb1.y,
          dz1 = va1.z - vb1.z, dw1 = va1.w - vb1.w;
    float sp0 = dx0*dx0 + dy0*dy0 + dz0*dz0 + dw0*dw0;
    float sp1 = dx1*dx1 + dy1*dy1 + dz1*dz1 + dw1*dw1;
    #pragma unroll
    for (int o = 16; o; o >>= 1) {
        s10 += __shfl_xor_sync(0xffffffffu, s10, o);
        s11 += __shfl_xor_sync(0xffffffffu, s11, o);
        s20 += __shfl_xor_sync(0xffffffffu, s20, o);
        s21 += __shfl_xor_sync(0xffffffffu, s21, o);
        sp0 += __shfl_xor_sync(0xffffffffu, sp0, o);
        sp1 += __shfl_xor_sync(0xffffffffu, sp1, o);
    }
    if (lane == 0) {
        g_sq1[r0] = s10;  g_sq1[r1] = s11;
        g_sq2[r0] = s20;  g_sq2[r1] = s21;
        g_f1[r0]  = s10 - (dA0 ? 1e9f : 0.0f);
        g_f1[r1]  = s11 - (dA1 ? 1e9f : 0.0f);
        g_f2[r0]  = s20 - (dB0 ? 1e9f : 0.0f);
        g_f2[r1]  = s21 - (dB1 ? 1e9f : 0.0f);
        g_possq[r0] = sp0;  g_possq[r1] = sp1;
    }
}

// ============================================================================
// Kernel 1: int8 IMMA tile (M=128, N=128, K=128) + filter epilogue.
// 256 threads = 8 warps (2 warp-rows x 4 warp-cols), warp tile 64x32.
// MMA loop byte-identical to the R5/R10/R12 optimum; only the epilogue's
// s1 source changed (global -> SMEM staged in the existing staging phase).
// ============================================================================
__global__ void __launch_bounds__(256, 2)
tile_kernel(const float* __restrict__ X1, const float* __restrict__ X2, int n) {
    extern __shared__ char smem[];
    const int tid  = threadIdx.x;
    const int l    = tid & 31;
    const int w    = tid >> 5;
    const int wrow = w >> 2;      // 0..1, 64 M-rows each
    const int wcol = w & 3;       // 0..3, 32 N-cols each
    const int i0   = blockIdx.y * BM;
    const int j0   = blockIdx.x * BN;

    // ---- stage A (128x128 s8) and B (128x128 s8), padded rows ----
    #pragma unroll
    for (int it = 0; it < 4; it++) {
        int idx = tid + it * 256;            // 0..1023 chunks of 16B
        int row = idx >> 3, ch = idx & 7;
        uint4 va = *reinterpret_cast<const uint4*>(
            g_a8 + (size_t)(i0 + row) * 128 + ch * 16);
        *reinterpret_cast<uint4*>(smem + SMEM_A + row * ROWB + ch * 16) = va;
        uint4 vb = *reinterpret_cast<const uint4*>(
            g_b8 + (size_t)(j0 + row) * 128 + ch * 16);
        *reinterpret_cast<uint4*>(smem + SMEM_B + row * ROWB + ch * 16) = vb;
    }
    if (tid < 128) {
        reinterpret_cast<float*>(smem + SMEM_H)[tid]  = g_f2[j0 + tid];
        reinterpret_cast<float*>(smem + SMEM_S1)[tid] = g_f1[i0 + tid];
    }
    __syncthreads();

    const uint32_t sbase = smem_u32(smem);
    const uint32_t a_addr = sbase + SMEM_A
        + (uint32_t)(wrow * 64 + (l & 7) + ((l >> 3) & 1) * 8) * ROWB
        + ((l >> 4) & 1) * 16;
    const uint32_t b_addr = sbase + SMEM_B
        + (uint32_t)(wcol * 32 + (l & 7)) * ROWB
        + ((l >> 3) & 1) * 16;

    int acc[4][4][4];
    #pragma unroll
    for (int mt = 0; mt < 4; mt++)
        #pragma unroll
        for (int nt = 0; nt < 4; nt++)
            #pragma unroll
            for (int e = 0; e < 4; e++) acc[mt][nt][e] = 0;

    #pragma unroll
    for (int ks = 0; ks < 4; ks++) {          // k32 per step
        uint32_t a[4][4], b[4][2];
        #pragma unroll
        for (int mt = 0; mt < 4; mt++)
            ldsm4(a[mt], a_addr + mt * 16 * ROWB + ks * 32);
        #pragma unroll
        for (int nt = 0; nt < 4; nt++)
            ldsm2(b[nt], b_addr + nt * 8 * ROWB + ks * 32);
        #pragma unroll
        for (int mt = 0; mt < 4; mt++)
            #pragma unroll
            for (int nt = 0; nt < 4; nt++)
                imma16832(acc[mt][nt], a[mt], b[nt]);
    }

    // ---- epilogue: filtered est, rare exact recompute, row sums ----
    const float* hs  = reinterpret_cast<const float*>(smem + SMEM_H);
    const float* s1s = reinterpret_cast<const float*>(smem + SMEM_S1);
    float s1a[4], s1b[4];
    #pragma unroll
    for (int mt = 0; mt < 4; mt++) {
        int r = wrow * 64 + mt * 16 + (l >> 2);
        s1a[mt] = s1s[r];
        s1b[mt] = s1s[r + 8];
    }
    float s2c[8];
    #pragma unroll
    for (int nt = 0; nt < 4; nt++) {
        s2c[nt*2]   = hs[wcol * 32 + nt * 8 + (l & 3) * 2];
        s2c[nt*2+1] = hs[wcol * 32 + nt * 8 + (l & 3) * 2 + 1];
    }

    float minsq = 1e30f;
    #pragma unroll
    for (int mt = 0; mt < 4; mt++)
        #pragma unroll
        for (int nt = 0; nt < 4; nt++) {
            float q0 = fmaf(-INV2S2, (float)acc[mt][nt][0], s1a[mt] + s2c[nt*2]);
            float q1 = fmaf(-INV2S2, (float)acc[mt][nt][1], s1a[mt] + s2c[nt*2+1]);
            float q2 = fmaf(-INV2S2, (float)acc[mt][nt][2], s1b[mt] + s2c[nt*2]);
            float q3 = fmaf(-INV2S2, (float)acc[mt][nt][3], s1b[mt] + s2c[nt*2+1]);
            minsq = fminf(minsq, fminf(fminf(q0, q1), fminf(q2, q3)));
        }

    float rsA[4], rsB[4];
    #pragma unroll
    for (int mt = 0; mt < 4; mt++) { rsA[mt] = 0.0f; rsB[mt] = 0.0f; }

    if (minsq < EST_CUT) {   // essentially never; exactness path
        #pragma unroll 1
        for (int mt = 0; mt < 4; mt++) {
            int iA = i0 + wrow * 64 + mt * 16 + (l >> 2);
            int iB = iA + 8;
            #pragma unroll 1
            for (int nt = 0; nt < 4; nt++) {
                #pragma unroll
                for (int e = 0; e < 4; e++) {
                    float s1v = (e < 2) ? s1a[mt] : s1b[mt];
                    float s2v = s2c[nt*2 + (e & 1)];
                    float est = fmaf(-INV2S2, (float)acc[mt][nt][e], s1v + s2v);
                    if (est < EST_CUT) {
                        int i = (e < 2) ? iA : iB;
                        int j = j0 + wcol * 32 + nt * 8 + (l & 3) * 2 + (e & 1);
                        const float* xr = X1 + (size_t)i * D;
                        const float* yr = X2 + (size_t)j * D;
                        float dot = 0.0f;
                        #pragma unroll 8
                        for (int k = 0; k < D; k++) dot = fmaf(xr[k], yr[k], dot);
                        float sq = fmaxf(g_sq1[i] + g_sq2[j] - 2.0f * dot, 0.0f);
                        if (sq < SQ_CUT) {
                            float v = expf(-sq);
                            if (e < 2) rsA[mt] += v; else rsB[mt] += v;
                        }
                    }
                }
            }
        }
    }

    // reduce over the 4 lanes that share each row
    float* part = reinterpret_cast<float*>(smem + SMEM_PART);
    #pragma unroll
    for (int mt = 0; mt < 4; mt++) {
        rsA[mt] += __shfl_xor_sync(0xffffffffu, rsA[mt], 1);
        rsA[mt] += __shfl_xor_sync(0xffffffffu, rsA[mt], 2);
        rsB[mt] += __shfl_xor_sync(0xffffffffu, rsB[mt], 1);
        rsB[mt] += __shfl_xor_sync(0xffffffffu, rsB[mt], 2);
        if ((l & 3) == 0) {
            int r = wrow * 64 + mt * 16 + (l >> 2);
            part[wcol * 128 + r]     = rsA[mt];
            part[wcol * 128 + r + 8] = rsB[mt];
        }
    }
    __syncthreads();
    if (tid < 128) {
        float s = part[tid] + part[128 + tid] + part[256 + tid] + part[384 + tid];
        g_part[(size_t)blockIdx.x * n + i0 + tid] = s;
    }
}

// ============================================================================
// Kernel 2: per-row finalize + per-block triple reduction (double accum).
// ============================================================================
__global__ void finalize_kernel(int n, int gtiles) {
    int i = blockIdx.x * blockDim.x + threadIdx.x;
    float s = 0.0f;
    for (int g = 0; g < gtiles; g++) s += g_part[(size_t)g * n + i];
    float rep = s / (float)n;
    float att = expf(-g_possq[i]);
    float li  = log1pf(rep / (att + 1e-8f));

    double v0 = (double)li, v1 = (double)att, v2 = (double)rep;
    #pragma unroll
    for (int o = 16; o; o >>= 1) {
        v0 += __shfl_down_sync(0xffffffffu, v0, o);
        v1 += __shfl_down_sync(0xffffffffu, v1, o);
        v2 += __shfl_down_sync(0xffffffffu, v2, o);
    }
    __shared__ double sm[3][8];
    int lane = threadIdx.x & 31, w = threadIdx.x >> 5;
    if (lane == 0) { sm[0][w] = v0; sm[1][w] = v1; sm[2][w] = v2; }
    __syncthreads();
    if (threadIdx.x == 0) {
        double t0 = 0, t1 = 0, t2 = 0;
        #pragma unroll
        for (int q = 0; q < 8; q++) { t0 += sm[0][q]; t1 += sm[1][q]; t2 += sm[2][q]; }
        g_blk[blockIdx.x][0] = t0;
        g_blk[blockIdx.x][1] = t1;
        g_blk[blockIdx.x][2] = t2;
    }
}

// ============================================================================
// Kernel 3: parallel final reduce (nb = 64).
// ============================================================================
__global__ void output_kernel(float* __restrict__ out, int n, int nb, int out_size) {
    int t = threadIdx.x;
    double v0 = 0, v1 = 0, v2 = 0;
    if (t < nb) { v0 = g_blk[t][0]; v1 = g_blk[t][1]; v2 = g_blk[t][2]; }
    #pragma unroll
    for (int o = 16; o; o >>= 1) {
        v0 += __shfl_down_sync(0xffffffffu, v0, o);
        v1 += __shfl_down_sync(0xffffffffu, v1, o);
        v2 += __shfl_down_sync(0xffffffffu, v2, o);
    }
    __shared__ double sm[3][2];
    int lane = t & 31, w = t >> 5;
    if (lane == 0) { sm[0][w] = v0; sm[1][w] = v1; sm[2][w] = v2; }
    __syncthreads();
    if (t == 0) {
        double t0 = sm[0][0] + sm[0][1];
        double t1 = sm[1][0] + sm[1][1];
        double t2 = sm[2][0] + sm[2][1];
        if (out_size > 0) out[0] = (float)(t0 / (double)n);
        if (out_size > 1) out[1] = (float)(t1 / (double)n);
        if (out_size > 2) out[2] = (float)(t2 / (double)n);
    }
}

extern "C" void kernel_launch(void* const* d_in, const int* in_sizes, int n_in,
                              void* d_out, int out_size) {
    const float* x1 = (const float*)d_in[0];
    const float* x2 = (const float*)d_in[1];
    int n = in_sizes[0] / D;              // 16384
    int gtiles = n / BN;                  // 128

    cudaFuncSetAttribute(tile_kernel,
                         cudaFuncAttributeMaxDynamicSharedMemorySize, SMEM_TOTAL);

    prep_kernel<<<(n / 2 * 32 + 255) / 256, 256>>>(x1, x2, n);

    dim3 grid(gtiles, n / BM);            // (128, 128)
    tile_kernel<<<grid, 256, SMEM_TOTAL>>>(x1, x2, n);

    finalize_kernel<<<n / 256, 256>>>(n, gtiles);
    output_kernel<<<1, 64>>>((float*)d_out, n, n / 256, out_size);
}

// round 14
// speedup vs baseline: 1.0114x; 1.0114x over previous
#include <cuda_runtime.h>
#include <cuda_bf16.h>
#include <math.h>
#include <stdint.h>

// ContrastiveLoss: N=16384, D=128.
// sq[i][j] = max(sq1[i]+sq2[j]-2*dot, 0); exp(-sq)==0 in fp32 for sq>~104.
// int8 mma.sync (m16n8k32.s8) GEMM as a coarse filter: q = round(20*x),
// dot ~= (s32 dot)/400, worst-case sq error < 14 -> EST_CUT=119 margin.
// Exact fp32 recompute for the (essentially never occurring) near pairs.
// Rows with any |20*x| > 127 get -1e9 bias on the filtered norm -> exact path.
//
// R14 = R12 byte-for-byte (measured optimum, 269.0 us; 269-270 cluster over
// three runs). Eight perturbations of this configuration (R6-R9, R11, R13,
// plus tile/occupancy variants) all measured neutral or negative; the
// remaining gap to the legacy-IMMA issue floor is locked behind ptxas
// scheduling, and tcgen05 is unreachable (harness PTX target: plain sm_100).
// FINAL.

#define D    128
#define BM   128
#define BN   128
#define NMAX 16384
#define GT_MAX (NMAX / BN)
#define SQ_CUT  105.0f
#define EST_CUT 119.0f
#define QS      20.0f        // quant scale
#define INV2S2  0.005f       // 2 / (QS*QS)

// ---- static device scratch ----
__device__ float  g_sq1[NMAX];     // clean |x1_i|^2
__device__ float  g_sq2[NMAX];     // clean |x2_j|^2
__device__ float  g_f1[NMAX];      // sq1 - (dirty ? 1e9 : 0)   (filter copy)
__device__ float  g_f2[NMAX];
__device__ float  g_possq[NMAX];
__device__ char   g_a8[(size_t)NMAX * D];
__device__ char   g_b8[(size_t)NMAX * D];
__device__ float  g_part[(size_t)GT_MAX * NMAX];
__device__ double g_blk[NMAX / 256][3];

// ---- SMEM layout: padded int8 rows, 144B stride (conflict-free ldmatrix) --
#define ROWB       144
#define SMEM_A     0
#define SMEM_B     (128 * ROWB)              // 18432
#define SMEM_PART  (2 * 128 * ROWB)          // 36864: float[4][128]
#define SMEM_H     (SMEM_PART + 2048)        // 38912: float[128] filtered sq2
#define SMEM_TOTAL (SMEM_H + 512 + 64)

__device__ __forceinline__ uint32_t smem_u32(const void* p) {
    uint32_t a;
    asm("{ .reg .u64 t; cvta.to.shared.u64 t, %1; cvt.u32.u64 %0, t; }"
        : "=r"(a) : "l"(p));
    return a;
}
__device__ __forceinline__ void ldsm4(uint32_t* r, uint32_t addr) {
    asm volatile("ldmatrix.sync.aligned.m8n8.x4.shared.b16 {%0,%1,%2,%3}, [%4];"
                 : "=r"(r[0]), "=r"(r[1]), "=r"(r[2]), "=r"(r[3]) : "r"(addr));
}
__device__ __forceinline__ void ldsm2(uint32_t* r, uint32_t addr) {
    asm volatile("ldmatrix.sync.aligned.m8n8.x2.shared.b16 {%0,%1}, [%2];"
                 : "=r"(r[0]), "=r"(r[1]) : "r"(addr));
}
__device__ __forceinline__ void imma16832(int* d, const uint32_t* a, const uint32_t* b) {
    asm volatile(
        "mma.sync.aligned.m16n8k32.row.col.s32.s8.s8.s32 "
        "{%0,%1,%2,%3}, {%4,%5,%6,%7}, {%8,%9}, {%0,%1,%2,%3};"
        : "+r"(d[0]), "+r"(d[1]), "+r"(d[2]), "+r"(d[3])
        : "r"(a[0]), "r"(a[1]), "r"(a[2]), "r"(a[3]), "r"(b[0]), "r"(b[1]));
}

__device__ __forceinline__ int quant1(float x, float& mx) {
    float f = x * QS;
    mx = fmaxf(mx, fabsf(f));
    f = fmaxf(fminf(f, 127.0f), -127.0f);
    return __float2int_rn(f);
}

// ============================================================================
// Kernel 0: row norms, pos_sq, int8 quant + dirty flags. 2 rows per warp
// (4 independent float4 loads per thread -> latency hiding; bytes unchanged).
// ============================================================================
__global__ void prep_kernel(const float* __restrict__ x1,
                            const float* __restrict__ x2, int n) {
    int warp = (blockIdx.x * blockDim.x + threadIdx.x) >> 5;
    int lane = threadIdx.x & 31;
    int r0 = warp * 2;
    if (r0 >= n) return;
    int r1 = r0 + 1;

    float4 va0 = reinterpret_cast<const float4*>(x1 + (size_t)r0 * D)[lane];
    float4 va1 = reinterpret_cast<const float4*>(x1 + (size_t)r1 * D)[lane];
    float4 vb0 = reinterpret_cast<const float4*>(x2 + (size_t)r0 * D)[lane];
    float4 vb1 = reinterpret_cast<const float4*>(x2 + (size_t)r1 * D)[lane];

    float mxa0 = 0.0f, mxb0 = 0.0f, mxa1 = 0.0f, mxb1 = 0.0f;
    char4 qa0, qb0, qa1, qb1;
    qa0.x = (char)quant1(va0.x, mxa0); qa0.y = (char)quant1(va0.y, mxa0);
    qa0.z = (char)quant1(va0.z, mxa0); qa0.w = (char)quant1(va0.w, mxa0);
    qa1.x = (char)quant1(va1.x, mxa1); qa1.y = (char)quant1(va1.y, mxa1);
    qa1.z = (char)quant1(va1.z, mxa1); qa1.w = (char)quant1(va1.w, mxa1);
    qb0.x = (char)quant1(vb0.x, mxb0); qb0.y = (char)quant1(vb0.y, mxb0);
    qb0.z = (char)quant1(vb0.z, mxb0); qb0.w = (char)quant1(vb0.w, mxb0);
    qb1.x = (char)quant1(vb1.x, mxb1); qb1.y = (char)quant1(vb1.y, mxb1);
    qb1.z = (char)quant1(vb1.z, mxb1); qb1.w = (char)quant1(vb1.w, mxb1);
    reinterpret_cast<char4*>(g_a8 + (size_t)r0 * D)[lane] = qa0;
    reinterpret_cast<char4*>(g_a8 + (size_t)r1 * D)[lane] = qa1;
    reinterpret_cast<char4*>(g_b8 + (size_t)r0 * D)[lane] = qb0;
    reinterpret_cast<char4*>(g_b8 + (size_t)r1 * D)[lane] = qb1;

    unsigned dA0 = __ballot_sync(0xffffffffu, mxa0 > 127.0f);
    unsigned dA1 = __ballot_sync(0xffffffffu, mxa1 > 127.0f);
    unsigned dB0 = __ballot_sync(0xffffffffu, mxb0 > 127.0f);
    unsigned dB1 = __ballot_sync(0xffffffffu, mxb1 > 127.0f);

    float s10 = va0.x*va0.x + va0.y*va0.y + va0.z*va0.z + va0.w*va0.w;
    float s11 = va1.x*va1.x + va1.y*va1.y + va1.z*va1.z + va1.w*va1.w;
    float s20 = vb0.x*vb0.x + vb0.y*vb0.y + vb0.z*vb0.z + vb0.w*vb0.w;
    float s21 = vb1.x*vb1.x + vb1.y*vb1.y + vb1.z*vb1.z + vb1.w*vb1.w;
    float dx0 = va0.x - vb0.x, dy0 = va0.y - vb0.y,
          dz0 = va0.z - vb0.z, dw0 = va0.w - vb0.w;
    float dx1 = va1.x - vb1.x, dy1 = va1.y - vb1.y,
          dz1 = va1.z - vb1.z, dw1 = va1.w - vb1.w;
    float sp0 = dx0*dx0 + dy0*dy0 + dz0*dz0 + dw0*dw0;
    float sp1 = dx1*dx1 + dy1*dy1 + dz1*dz1 + dw1*dw1;
    #pragma unroll
    for (int o = 16; o; o >>= 1) {
        s10 += __shfl_xor_sync(0xffffffffu, s10, o);
        s11 += __shfl_xor_sync(0xffffffffu, s11, o);
        s20 += __shfl_xor_sync(0xffffffffu, s20, o);
        s21 += __shfl_xor_sync(0xffffffffu, s21, o);
        sp0 += __shfl_xor_sync(0xffffffffu, sp0, o);
        sp1 += __shfl_xor_sync(0xffffffffu, sp1, o);
    }
    if (lane == 0) {
        g_sq1[r0] = s10;  g_sq1[r1] = s11;
        g_sq2[r0] = s20;  g_sq2[r1] = s21;
        g_f1[r0]  = s10 - (dA0 ? 1e9f : 0.0f);
        g_f1[r1]  = s11 - (dA1 ? 1e9f : 0.0f);
        g_f2[r0]  = s20 - (dB0 ? 1e9f : 0.0f);
        g_f2[r1]  = s21 - (dB1 ? 1e9f : 0.0f);
        g_possq[r0] = sp0;  g_possq[r1] = sp1;
    }
}

// ============================================================================
// Kernel 1: int8 IMMA tile (M=128, N=128, K=128) + filter epilogue.
// 256 threads = 8 warps (2 warp-rows x 4 warp-cols), warp tile 64x32.
// (Byte-identical to the measured R5/R10/R12 optimum.)
// ============================================================================
__global__ void __launch_bounds__(256, 2)
tile_kernel(const float* __restrict__ X1, const float* __restrict__ X2, int n) {
    extern __shared__ char smem[];
    const int tid  = threadIdx.x;
    const int l    = tid & 31;
    const int w    = tid >> 5;
    const int wrow = w >> 2;      // 0..1, 64 M-rows each
    const int wcol = w & 3;       // 0..3, 32 N-cols each
    const int i0   = blockIdx.y * BM;
    const int j0   = blockIdx.x * BN;

    // ---- stage A (128x128 s8) and B (128x128 s8), padded rows ----
    #pragma unroll
    for (int it = 0; it < 4; it++) {
        int idx = tid + it * 256;            // 0..1023 chunks of 16B
        int row = idx >> 3, ch = idx & 7;
        uint4 va = *reinterpret_cast<const uint4*>(
            g_a8 + (size_t)(i0 + row) * 128 + ch * 16);
        *reinterpret_cast<uint4*>(smem + SMEM_A + row * ROWB + ch * 16) = va;
        uint4 vb = *reinterpret_cast<const uint4*>(
            g_b8 + (size_t)(j0 + row) * 128 + ch * 16);
        *reinterpret_cast<uint4*>(smem + SMEM_B + row * ROWB + ch * 16) = vb;
    }
    if (tid < 128)
        reinterpret_cast<float*>(smem + SMEM_H)[tid] = g_f2[j0 + tid];
    __syncthreads();

    const uint32_t sbase = smem_u32(smem);
    const uint32_t a_addr = sbase + SMEM_A
        + (uint32_t)(wrow * 64 + (l & 7) + ((l >> 3) & 1) * 8) * ROWB
        + ((l >> 4) & 1) * 16;
    const uint32_t b_addr = sbase + SMEM_B
        + (uint32_t)(wcol * 32 + (l & 7)) * ROWB
        + ((l >> 3) & 1) * 16;

    int acc[4][4][4];
    #pragma unroll
    for (int mt = 0; mt < 4; mt++)
        #pragma unroll
        for (int nt = 0; nt < 4; nt++)
            #pragma unroll
            for (int e = 0; e < 4; e++) acc[mt][nt][e] = 0;

    #pragma unroll
    for (int ks = 0; ks < 4; ks++) {          // k32 per step
        uint32_t a[4][4], b[4][2];
        #pragma unroll
        for (int mt = 0; mt < 4; mt++)
            ldsm4(a[mt], a_addr + mt * 16 * ROWB + ks * 32);
        #pragma unroll
        for (int nt = 0; nt < 4; nt++)
            ldsm2(b[nt], b_addr + nt * 8 * ROWB + ks * 32);
        #pragma unroll
        for (int mt = 0; mt < 4; mt++)
            #pragma unroll
            for (int nt = 0; nt < 4; nt++)
                imma16832(acc[mt][nt], a[mt], b[nt]);
    }

    // ---- epilogue: filtered est, rare exact recompute, row sums ----
    const float* hs = reinterpret_cast<const float*>(smem + SMEM_H);
    float s1a[4], s1b[4];
    #pragma unroll
    for (int mt = 0; mt < 4; mt++) {
        int r = wrow * 64 + mt * 16 + (l >> 2);
        s1a[mt] = g_f1[i0 + r];
        s1b[mt] = g_f1[i0 + r + 8];
    }
    float s2c[8];
    #pragma unroll
    for (int nt = 0; nt < 4; nt++) {
        s2c[nt*2]   = hs[wcol * 32 + nt * 8 + (l & 3) * 2];
        s2c[nt*2+1] = hs[wcol * 32 + nt * 8 + (l & 3) * 2 + 1];
    }

    float minsq = 1e30f;
    #pragma unroll
    for (int mt = 0; mt < 4; mt++)
        #pragma unroll
        for (int nt = 0; nt < 4; nt++) {
            float q0 = fmaf(-INV2S2, (float)acc[mt][nt][0], s1a[mt] + s2c[nt*2]);
            float q1 = fmaf(-INV2S2, (float)acc[mt][nt][1], s1a[mt] + s2c[nt*2+1]);
            float q2 = fmaf(-INV2S2, (float)acc[mt][nt][2], s1b[mt] + s2c[nt*2]);
            float q3 = fmaf(-INV2S2, (float)acc[mt][nt][3], s1b[mt] + s2c[nt*2+1]);
            minsq = fminf(minsq, fminf(fminf(q0, q1), fminf(q2, q3)));
        }

    float rsA[4], rsB[4];
    #pragma unroll
    for (int mt = 0; mt < 4; mt++) { rsA[mt] = 0.0f; rsB[mt] = 0.0f; }

    if (minsq < EST_CUT) {   // essentially never; exactness path
        #pragma unroll 1
        for (int mt = 0; mt < 4; mt++) {
            int iA = i0 + wrow * 64 + mt * 16 + (l >> 2);
            int iB = iA + 8;
            #pragma unroll 1
            for (int nt = 0; nt < 4; nt++) {
                #pragma unroll
                for (int e = 0; e < 4; e++) {
                    float s1v = (e < 2) ? s1a[mt] : s1b[mt];
                    float s2v = s2c[nt*2 + (e & 1)];
                    float est = fmaf(-INV2S2, (float)acc[mt][nt][e], s1v + s2v);
                    if (est < EST_CUT) {
                        int i = (e < 2) ? iA : iB;
                        int j = j0 + wcol * 32 + nt * 8 + (l & 3) * 2 + (e & 1);
                        const float* xr = X1 + (size_t)i * D;
                        const float* yr = X2 + (size_t)j * D;
                        float dot = 0.0f;
                        #pragma unroll 8
                        for (int k = 0; k < D; k++) dot = fmaf(xr[k], yr[k], dot);
                        float sq = fmaxf(g_sq1[i] + g_sq2[j] - 2.0f * dot, 0.0f);
                        if (sq < SQ_CUT) {
                            float v = expf(-sq);
                            if (e < 2) rsA[mt] += v; else rsB[mt] += v;
                        }
                    }
                }
            }
        }
    }

    // reduce over the 4 lanes that share each row
    float* part = reinterpret_cast<float*>(smem + SMEM_PART);
    #pragma unroll
    for (int mt = 0; mt < 4; mt++) {
        rsA[mt] += __shfl_xor_sync(0xffffffffu, rsA[mt], 1);
        rsA[mt] += __shfl_xor_sync(0xffffffffu, rsA[mt], 2);
        rsB[mt] += __shfl_xor_sync(0xffffffffu, rsB[mt], 1);
        rsB[mt] += __shfl_xor_sync(0xffffffffu, rsB[mt], 2);
        if ((l & 3) == 0) {
            int r = wrow * 64 + mt * 16 + (l >> 2);
            part[wcol * 128 + r]     = rsA[mt];
            part[wcol * 128 + r + 8] = rsB[mt];
        }
    }
    __syncthreads();
    if (tid < 128) {
        float s = part[tid] + part[128 + tid] + part[256 + tid] + part[384 + tid];
        g_part[(size_t)blockIdx.x * n + i0 + tid] = s;
    }
}

// ============================================================================
// Kernel 2: per-row finalize + per-block triple reduction (double accum).
// ============================================================================
__global__ void finalize_kernel(int n, int gtiles) {
    int i = blockIdx.x * blockDim.x + threadIdx.x;
    float s = 0.0f;
    for (int g = 0; g < gtiles; g++) s += g_part[(size_t)g * n + i];
    float rep = s / (float)n;
    float att = expf(-g_possq[i]);
    float li  = log1pf(rep / (att + 1e-8f));

    double v0 = (double)li, v1 = (double)att, v2 = (double)rep;
    #pragma unroll
    for (int o = 16; o; o >>= 1) {
        v0 += __shfl_down_sync(0xffffffffu, v0, o);
        v1 += __shfl_down_sync(0xffffffffu, v1, o);
        v2 += __shfl_down_sync(0xffffffffu, v2, o);
    }
    __shared__ double sm[3][8];
    int lane = threadIdx.x & 31, w = threadIdx.x >> 5;
    if (lane == 0) { sm[0][w] = v0; sm[1][w] = v1; sm[2][w] = v2; }
    __syncthreads();
    if (threadIdx.x == 0) {
        double t0 = 0, t1 = 0, t2 = 0;
        #pragma unroll
        for (int q = 0; q < 8; q++) { t0 += sm[0][q]; t1 += sm[1][q]; t2 += sm[2][q]; }
        g_blk[blockIdx.x][0] = t0;
        g_blk[blockIdx.x][1] = t1;
        g_blk[blockIdx.x][2] = t2;
    }
}

// ============================================================================
// Kernel 3: parallel final reduce (nb = 64).
// ============================================================================
__global__ void output_kernel(float* __restrict__ out, int n, int nb, int out_size) {
    int t = threadIdx.x;
    double v0 = 0, v1 = 0, v2 = 0;
    if (t < nb) { v0 = g_blk[t][0]; v1 = g_blk[t][1]; v2 = g_blk[t][2]; }
    #pragma unroll
    for (int o = 16; o; o >>= 1) {
        v0 += __shfl_down_sync(0xffffffffu, v0, o);
        v1 += __shfl_down_sync(0xffffffffu, v1, o);
        v2 += __shfl_down_sync(0xffffffffu, v2, o);
    }
    __shared__ double sm[3][2];
    int lane = t & 31, w = t >> 5;
    if (lane == 0) { sm[0][w] = v0; sm[1][w] = v1; sm[2][w] = v2; }
    __syncthreads();
    if (t == 0) {
        double t0 = sm[0][0] + sm[0][1];
        double t1 = sm[1][0] + sm[1][1];
        double t2 = sm[2][0] + sm[2][1];
        if (out_size > 0) out[0] = (float)(t0 / (double)n);
        if (out_size > 1) out[1] = (float)(t1 / (double)n);
        if (out_size > 2) out[2] = (float)(t2 / (double)n);
    }
}

extern "C" void kernel_launch(void* const* d_in, const int* in_sizes, int n_in,
                              void* d_out, int out_size) {
    const float* x1 = (const float*)d_in[0];
    const float* x2 = (const float*)d_in[1];
    int n = in_sizes[0] / D;              // 16384
    int gtiles = n / BN;                  // 128

    cudaFuncSetAttribute(tile_kernel,
                         cudaFuncAttributeMaxDynamicSharedMemorySize, SMEM_TOTAL);

    prep_kernel<<<(n / 2 * 32 + 255) / 256, 256>>>(x1, x2, n);

    dim3 grid(gtiles, n / BM);            // (128, 128)
    tile_kernel<<<grid, 256, SMEM_TOTAL>>>(x1, x2, n);

    finalize_kernel<<<n / 256, 256>>>(n, gtiles);
    output_kernel<<<1, 64>>>((float*)d_out, n, n / 256, out_size);
}

// round 15
// speedup vs baseline: 1.0159x; 1.0044x over previous
#include <cuda_runtime.h>
#include <cuda_bf16.h>
#include <math.h>
#include <stdint.h>

// ContrastiveLoss: N=16384, D=128.
// sq[i][j] = max(sq1[i]+sq2[j]-2*dot, 0); exp(-sq)==0 in fp32 for sq>~104.
// int8 mma.sync (m16n8k32.s8) GEMM as a coarse filter: q = round(20*x),
// dot ~= (s32 dot)/400, worst-case sq error < 14 -> EST_CUT=119 margin.
// Exact fp32 recompute for the (essentially never occurring) near pairs.
// Rows with any |20*x| > 127 get -1e9 bias on the filtered norm -> exact path.
//
// FINAL (R15 = R12, the measured optimum: 269.0 / 269.3 / 270.3 / 272.4 us
// over four runs, rel_err 0.0). Session ledger: 3 structural wins
// (underflow-filter reformulation 1483us, bf16 HMMA 353us, int8 IMMA 270us);
// 9 perturbations of this configuration all neutral-or-negative. Residual
// gap to the legacy-IMMA issue floor is locked behind ptxas scheduling of
// the unrolled MMA stream; tcgen05 unreachable (harness PTX target sm_100).

#define D    128
#define BM   128
#define BN   128
#define NMAX 16384
#define GT_MAX (NMAX / BN)
#define SQ_CUT  105.0f
#define EST_CUT 119.0f
#define QS      20.0f        // quant scale
#define INV2S2  0.005f       // 2 / (QS*QS)

// ---- static device scratch ----
__device__ float  g_sq1[NMAX];     // clean |x1_i|^2
__device__ float  g_sq2[NMAX];     // clean |x2_j|^2
__device__ float  g_f1[NMAX];      // sq1 - (dirty ? 1e9 : 0)   (filter copy)
__device__ float  g_f2[NMAX];
__device__ float  g_possq[NMAX];
__device__ char   g_a8[(size_t)NMAX * D];
__device__ char   g_b8[(size_t)NMAX * D];
__device__ float  g_part[(size_t)GT_MAX * NMAX];
__device__ double g_blk[NMAX / 256][3];

// ---- SMEM layout: padded int8 rows, 144B stride (conflict-free ldmatrix) --
#define ROWB       144
#define SMEM_A     0
#define SMEM_B     (128 * ROWB)              // 18432
#define SMEM_PART  (2 * 128 * ROWB)          // 36864: float[4][128]
#define SMEM_H     (SMEM_PART + 2048)        // 38912: float[128] filtered sq2
#define SMEM_TOTAL (SMEM_H + 512 + 64)

__device__ __forceinline__ uint32_t smem_u32(const void* p) {
    uint32_t a;
    asm("{ .reg .u64 t; cvta.to.shared.u64 t, %1; cvt.u32.u64 %0, t; }"
        : "=r"(a) : "l"(p));
    return a;
}
__device__ __forceinline__ void ldsm4(uint32_t* r, uint32_t addr) {
    asm volatile("ldmatrix.sync.aligned.m8n8.x4.shared.b16 {%0,%1,%2,%3}, [%4];"
                 : "=r"(r[0]), "=r"(r[1]), "=r"(r[2]), "=r"(r[3]) : "r"(addr));
}
__device__ __forceinline__ void ldsm2(uint32_t* r, uint32_t addr) {
    asm volatile("ldmatrix.sync.aligned.m8n8.x2.shared.b16 {%0,%1}, [%2];"
                 : "=r"(r[0]), "=r"(r[1]) : "r"(addr));
}
__device__ __forceinline__ void imma16832(int* d, const uint32_t* a, const uint32_t* b) {
    asm volatile(
        "mma.sync.aligned.m16n8k32.row.col.s32.s8.s8.s32 "
        "{%0,%1,%2,%3}, {%4,%5,%6,%7}, {%8,%9}, {%0,%1,%2,%3};"
        : "+r"(d[0]), "+r"(d[1]), "+r"(d[2]), "+r"(d[3])
        : "r"(a[0]), "r"(a[1]), "r"(a[2]), "r"(a[3]), "r"(b[0]), "r"(b[1]));
}

__device__ __forceinline__ int quant1(float x, float& mx) {
    float f = x * QS;
    mx = fmaxf(mx, fabsf(f));
    f = fmaxf(fminf(f, 127.0f), -127.0f);
    return __float2int_rn(f);
}

// ============================================================================
// Kernel 0: row norms, pos_sq, int8 quant + dirty flags. 2 rows per warp
// (4 independent float4 loads per thread -> latency hiding; bytes unchanged).
// ============================================================================
__global__ void prep_kernel(const float* __restrict__ x1,
                            const float* __restrict__ x2, int n) {
    int warp = (blockIdx.x * blockDim.x + threadIdx.x) >> 5;
    int lane = threadIdx.x & 31;
    int r0 = warp * 2;
    if (r0 >= n) return;
    int r1 = r0 + 1;

    float4 va0 = reinterpret_cast<const float4*>(x1 + (size_t)r0 * D)[lane];
    float4 va1 = reinterpret_cast<const float4*>(x1 + (size_t)r1 * D)[lane];
    float4 vb0 = reinterpret_cast<const float4*>(x2 + (size_t)r0 * D)[lane];
    float4 vb1 = reinterpret_cast<const float4*>(x2 + (size_t)r1 * D)[lane];

    float mxa0 = 0.0f, mxb0 = 0.0f, mxa1 = 0.0f, mxb1 = 0.0f;
    char4 qa0, qb0, qa1, qb1;
    qa0.x = (char)quant1(va0.x, mxa0); qa0.y = (char)quant1(va0.y, mxa0);
    qa0.z = (char)quant1(va0.z, mxa0); qa0.w = (char)quant1(va0.w, mxa0);
    qa1.x = (char)quant1(va1.x, mxa1); qa1.y = (char)quant1(va1.y, mxa1);
    qa1.z = (char)quant1(va1.z, mxa1); qa1.w = (char)quant1(va1.w, mxa1);
    qb0.x = (char)quant1(vb0.x, mxb0); qb0.y = (char)quant1(vb0.y, mxb0);
    qb0.z = (char)quant1(vb0.z, mxb0); qb0.w = (char)quant1(vb0.w, mxb0);
    qb1.x = (char)quant1(vb1.x, mxb1); qb1.y = (char)quant1(vb1.y, mxb1);
    qb1.z = (char)quant1(vb1.z, mxb1); qb1.w = (char)quant1(vb1.w, mxb1);
    reinterpret_cast<char4*>(g_a8 + (size_t)r0 * D)[lane] = qa0;
    reinterpret_cast<char4*>(g_a8 + (size_t)r1 * D)[lane] = qa1;
    reinterpret_cast<char4*>(g_b8 + (size_t)r0 * D)[lane] = qb0;
    reinterpret_cast<char4*>(g_b8 + (size_t)r1 * D)[lane] = qb1;

    unsigned dA0 = __ballot_sync(0xffffffffu, mxa0 > 127.0f);
    unsigned dA1 = __ballot_sync(0xffffffffu, mxa1 > 127.0f);
    unsigned dB0 = __ballot_sync(0xffffffffu, mxb0 > 127.0f);
    unsigned dB1 = __ballot_sync(0xffffffffu, mxb1 > 127.0f);

    float s10 = va0.x*va0.x + va0.y*va0.y + va0.z*va0.z + va0.w*va0.w;
    float s11 = va1.x*va1.x + va1.y*va1.y + va1.z*va1.z + va1.w*va1.w;
    float s20 = vb0.x*vb0.x + vb0.y*vb0.y + vb0.z*vb0.z + vb0.w*vb0.w;
    float s21 = vb1.x*vb1.x + vb1.y*vb1.y + vb1.z*vb1.z + vb1.w*vb1.w;
    float dx0 = va0.x - vb0.x, dy0 = va0.y - vb0.y,
          dz0 = va0.z - vb0.z, dw0 = va0.w - vb0.w;
    float dx1 = va1.x - vb1.x, dy1 = va1.y - vb1.y,
          dz1 = va1.z - vb1.z, dw1 = va1.w - vb1.w;
    float sp0 = dx0*dx0 + dy0*dy0 + dz0*dz0 + dw0*dw0;
    float sp1 = dx1*dx1 + dy1*dy1 + dz1*dz1 + dw1*dw1;
    #pragma unroll
    for (int o = 16; o; o >>= 1) {
        s10 += __shfl_xor_sync(0xffffffffu, s10, o);
        s11 += __shfl_xor_sync(0xffffffffu, s11, o);
        s20 += __shfl_xor_sync(0xffffffffu, s20, o);
        s21 += __shfl_xor_sync(0xffffffffu, s21, o);
        sp0 += __shfl_xor_sync(0xffffffffu, sp0, o);
        sp1 += __shfl_xor_sync(0xffffffffu, sp1, o);
    }
    if (lane == 0) {
        g_sq1[r0] = s10;  g_sq1[r1] = s11;
        g_sq2[r0] = s20;  g_sq2[r1] = s21;
        g_f1[r0]  = s10 - (dA0 ? 1e9f : 0.0f);
        g_f1[r1]  = s11 - (dA1 ? 1e9f : 0.0f);
        g_f2[r0]  = s20 - (dB0 ? 1e9f : 0.0f);
        g_f2[r1]  = s21 - (dB1 ? 1e9f : 0.0f);
        g_possq[r0] = sp0;  g_possq[r1] = sp1;
    }
}

// ============================================================================
// Kernel 1: int8 IMMA tile (M=128, N=128, K=128) + filter epilogue.
// 256 threads = 8 warps (2 warp-rows x 4 warp-cols), warp tile 64x32.
// (Byte-identical to the measured R5/R10/R12 optimum.)
// ============================================================================
__global__ void __launch_bounds__(256, 2)
tile_kernel(const float* __restrict__ X1, const float* __restrict__ X2, int n) {
    extern __shared__ char smem[];
    const int tid  = threadIdx.x;
    const int l    = tid & 31;
    const int w    = tid >> 5;
    const int wrow = w >> 2;      // 0..1, 64 M-rows each
    const int wcol = w & 3;       // 0..3, 32 N-cols each
    const int i0   = blockIdx.y * BM;
    const int j0   = blockIdx.x * BN;

    // ---- stage A (128x128 s8) and B (128x128 s8), padded rows ----
    #pragma unroll
    for (int it = 0; it < 4; it++) {
        int idx = tid + it * 256;            // 0..1023 chunks of 16B
        int row = idx >> 3, ch = idx & 7;
        uint4 va = *reinterpret_cast<const uint4*>(
            g_a8 + (size_t)(i0 + row) * 128 + ch * 16);
        *reinterpret_cast<uint4*>(smem + SMEM_A + row * ROWB + ch * 16) = va;
        uint4 vb = *reinterpret_cast<const uint4*>(
            g_b8 + (size_t)(j0 + row) * 128 + ch * 16);
        *reinterpret_cast<uint4*>(smem + SMEM_B + row * ROWB + ch * 16) = vb;
    }
    if (tid < 128)
        reinterpret_cast<float*>(smem + SMEM_H)[tid] = g_f2[j0 + tid];
    __syncthreads();

    const uint32_t sbase = smem_u32(smem);
    const uint32_t a_addr = sbase + SMEM_A
        + (uint32_t)(wrow * 64 + (l & 7) + ((l >> 3) & 1) * 8) * ROWB
        + ((l >> 4) & 1) * 16;
    const uint32_t b_addr = sbase + SMEM_B
        + (uint32_t)(wcol * 32 + (l & 7)) * ROWB
        + ((l >> 3) & 1) * 16;

    int acc[4][4][4];
    #pragma unroll
    for (int mt = 0; mt < 4; mt++)
        #pragma unroll
        for (int nt = 0; nt < 4; nt++)
            #pragma unroll
            for (int e = 0; e < 4; e++) acc[mt][nt][e] = 0;

    #pragma unroll
    for (int ks = 0; ks < 4; ks++) {          // k32 per step
        uint32_t a[4][4], b[4][2];
        #pragma unroll
        for (int mt = 0; mt < 4; mt++)
            ldsm4(a[mt], a_addr + mt * 16 * ROWB + ks * 32);
        #pragma unroll
        for (int nt = 0; nt < 4; nt++)
            ldsm2(b[nt], b_addr + nt * 8 * ROWB + ks * 32);
        #pragma unroll
        for (int mt = 0; mt < 4; mt++)
            #pragma unroll
            for (int nt = 0; nt < 4; nt++)
                imma16832(acc[mt][nt], a[mt], b[nt]);
    }

    // ---- epilogue: filtered est, rare exact recompute, row sums ----
    const float* hs = reinterpret_cast<const float*>(smem + SMEM_H);
    float s1a[4], s1b[4];
    #pragma unroll
    for (int mt = 0; mt < 4; mt++) {
        int r = wrow * 64 + mt * 16 + (l >> 2);
        s1a[mt] = g_f1[i0 + r];
        s1b[mt] = g_f1[i0 + r + 8];
    }
    float s2c[8];
    #pragma unroll
    for (int nt = 0; nt < 4; nt++) {
        s2c[nt*2]   = hs[wcol * 32 + nt * 8 + (l & 3) * 2];
        s2c[nt*2+1] = hs[wcol * 32 + nt * 8 + (l & 3) * 2 + 1];
    }

    float minsq = 1e30f;
    #pragma unroll
    for (int mt = 0; mt < 4; mt++)
        #pragma unroll
        for (int nt = 0; nt < 4; nt++) {
            float q0 = fmaf(-INV2S2, (float)acc[mt][nt][0], s1a[mt] + s2c[nt*2]);
            float q1 = fmaf(-INV2S2, (float)acc[mt][nt][1], s1a[mt] + s2c[nt*2+1]);
            float q2 = fmaf(-INV2S2, (float)acc[mt][nt][2], s1b[mt] + s2c[nt*2]);
            float q3 = fmaf(-INV2S2, (float)acc[mt][nt][3], s1b[mt] + s2c[nt*2+1]);
            minsq = fminf(minsq, fminf(fminf(q0, q1), fminf(q2, q3)));
        }

    float rsA[4], rsB[4];
    #pragma unroll
    for (int mt = 0; mt < 4; mt++) { rsA[mt] = 0.0f; rsB[mt] = 0.0f; }

    if (minsq < EST_CUT) {   // essentially never; exactness path
        #pragma unroll 1
        for (int mt = 0; mt < 4; mt++) {
            int iA = i0 + wrow * 64 + mt * 16 + (l >> 2);
            int iB = iA + 8;
            #pragma unroll 1
            for (int nt = 0; nt < 4; nt++) {
                #pragma unroll
                for (int e = 0; e < 4; e++) {
                    float s1v = (e < 2) ? s1a[mt] : s1b[mt];
                    float s2v = s2c[nt*2 + (e & 1)];
                    float est = fmaf(-INV2S2, (float)acc[mt][nt][e], s1v + s2v);
                    if (est < EST_CUT) {
                        int i = (e < 2) ? iA : iB;
                        int j = j0 + wcol * 32 + nt * 8 + (l & 3) * 2 + (e & 1);
                        const float* xr = X1 + (size_t)i * D;
                        const float* yr = X2 + (size_t)j * D;
                        float dot = 0.0f;
                        #pragma unroll 8
                        for (int k = 0; k < D; k++) dot = fmaf(xr[k], yr[k], dot);
                        float sq = fmaxf(g_sq1[i] + g_sq2[j] - 2.0f * dot, 0.0f);
                        if (sq < SQ_CUT) {
                            float v = expf(-sq);
                            if (e < 2) rsA[mt] += v; else rsB[mt] += v;
                        }
                    }
                }
            }
        }
    }

    // reduce over the 4 lanes that share each row
    float* part = reinterpret_cast<float*>(smem + SMEM_PART);
    #pragma unroll
    for (int mt = 0; mt < 4; mt++) {
        rsA[mt] += __shfl_xor_sync(0xffffffffu, rsA[mt], 1);
        rsA[mt] += __shfl_xor_sync(0xffffffffu, rsA[mt], 2);
        rsB[mt] += __shfl_xor_sync(0xffffffffu, rsB[mt], 1);
        rsB[mt] += __shfl_xor_sync(0xffffffffu, rsB[mt], 2);
        if ((l & 3) == 0) {
            int r = wrow * 64 + mt * 16 + (l >> 2);
            part[wcol * 128 + r]     = rsA[mt];
            part[wcol * 128 + r + 8] = rsB[mt];
        }
    }
    __syncthreads();
    if (tid < 128) {
        float s = part[tid] + part[128 + tid] + part[256 + tid] + part[384 + tid];
        g_part[(size_t)blockIdx.x * n + i0 + tid] = s;
    }
}

// ============================================================================
// Kernel 2: per-row finalize + per-block triple reduction (double accum).
// ============================================================================
__global__ void finalize_kernel(int n, int gtiles) {
    int i = blockIdx.x * blockDim.x + threadIdx.x;
    float s = 0.0f;
    for (int g = 0; g < gtiles; g++) s += g_part[(size_t)g * n + i];
    float rep = s / (float)n;
    float att = expf(-g_possq[i]);
    float li  = log1pf(rep / (att + 1e-8f));

    double v0 = (double)li, v1 = (double)att, v2 = (double)rep;
    #pragma unroll
    for (int o = 16; o; o >>= 1) {
        v0 += __shfl_down_sync(0xffffffffu, v0, o);
        v1 += __shfl_down_sync(0xffffffffu, v1, o);
        v2 += __shfl_down_sync(0xffffffffu, v2, o);
    }
    __shared__ double sm[3][8];
    int lane = threadIdx.x & 31, w = threadIdx.x >> 5;
    if (lane == 0) { sm[0][w] = v0; sm[1][w] = v1; sm[2][w] = v2; }
    __syncthreads();
    if (threadIdx.x == 0) {
        double t0 = 0, t1 = 0, t2 = 0;
        #pragma unroll
        for (int q = 0; q < 8; q++) { t0 += sm[0][q]; t1 += sm[1][q]; t2 += sm[2][q]; }
        g_blk[blockIdx.x][0] = t0;
        g_blk[blockIdx.x][1] = t1;
        g_blk[blockIdx.x][2] = t2;
    }
}

// ============================================================================
// Kernel 3: parallel final reduce (nb = 64).
// ============================================================================
__global__ void output_kernel(float* __restrict__ out, int n, int nb, int out_size) {
    int t = threadIdx.x;
    double v0 = 0, v1 = 0, v2 = 0;
    if (t < nb) { v0 = g_blk[t][0]; v1 = g_blk[t][1]; v2 = g_blk[t][2]; }
    #pragma unroll
    for (int o = 16; o; o >>= 1) {
        v0 += __shfl_down_sync(0xffffffffu, v0, o);
        v1 += __shfl_down_sync(0xffffffffu, v1, o);
        v2 += __shfl_down_sync(0xffffffffu, v2, o);
    }
    __shared__ double sm[3][2];
    int lane = t & 31, w = t >> 5;
    if (lane == 0) { sm[0][w] = v0; sm[1][w] = v1; sm[2][w] = v2; }
    __syncthreads();
    if (t == 0) {
        double t0 = sm[0][0] + sm[0][1];
        double t1 = sm[1][0] + sm[1][1];
        double t2 = sm[2][0] + sm[2][1];
        if (out_size > 0) out[0] = (float)(t0 / (double)n);
        if (out_size > 1) out[1] = (float)(t1 / (double)n);
        if (out_size > 2) out[2] = (float)(t2 / (double)n);
    }
}

extern "C" void kernel_launch(void* const* d_in, const int* in_sizes, int n_in,
                              void* d_out, int out_size) {
    const float* x1 = (const float*)d_in[0];
    const float* x2 = (const float*)d_in[1];
    int n = in_sizes[0] / D;              // 16384
    int gtiles = n / BN;                  // 128

    cudaFuncSetAttribute(tile_kernel,
                         cudaFuncAttributeMaxDynamicSharedMemorySize, SMEM_TOTAL);

    prep_kernel<<<(n / 2 * 32 + 255) / 256, 256>>>(x1, x2, n);

    dim3 grid(gtiles, n / BM);            // (128, 128)
    tile_kernel<<<grid, 256, SMEM_TOTAL>>>(x1, x2, n);

    finalize_kernel<<<n / 256, 256>>>(n, gtiles);
    output_kernel<<<1, 64>>>((float*)d_out, n, n / 256, out_size);
}